// round 7
// baseline (speedup 1.0000x reference)
#include <cuda_runtime.h>
#include <math.h>

#define B 4
#define S 2048
#define D 512
#define H 8
#define A 64
#define HA (H*A)

// Scratch (allocation-free rule: __device__ globals)
__device__ float g_q[(size_t)B*H*S*A];     // proj outputs, tf32-rounded
__device__ float g_k[(size_t)B*H*S*A];
__device__ float g_v[(size_t)B*H*S*A];
__device__ float g_attn[(size_t)B*S*HA];   // attention out, tf32-rounded
// tf32-rounded copies of inputs/weights (pre-pass)
__device__ float g_xq[(size_t)B*S*D];
__device__ float g_xk[(size_t)B*S*D];
__device__ float g_xv[(size_t)B*S*D];
__device__ float g_wq[(size_t)H*D*A];
__device__ float g_wk[(size_t)H*D*A];
__device__ float g_wv[(size_t)H*D*A];
__device__ float g_wo[(size_t)HA*D];

// ---------------------------------------------------------------------------
// helpers
// ---------------------------------------------------------------------------
__device__ __forceinline__ unsigned f2tf(float x) {
    unsigned u;
    asm("cvt.rna.tf32.f32 %0, %1;" : "=r"(u) : "f"(x));
    return u;
}

__device__ __forceinline__ void mma_tf32(float c[4], const unsigned a[4],
                                         unsigned b0, unsigned b1) {
    asm volatile("mma.sync.aligned.m16n8k8.row.col.f32.tf32.tf32.f32 "
                 "{%0,%1,%2,%3}, {%4,%5,%6,%7}, {%8,%9}, {%0,%1,%2,%3};"
                 : "+f"(c[0]), "+f"(c[1]), "+f"(c[2]), "+f"(c[3])
                 : "r"(a[0]), "r"(a[1]), "r"(a[2]), "r"(a[3]),
                   "r"(b0), "r"(b1));
}

__device__ __forceinline__ void cpa16(float* dst_smem, const float* src) {
    unsigned d = (unsigned)__cvta_generic_to_shared(dst_smem);
    asm volatile("cp.async.cg.shared.global [%0], [%1], 16;" :: "r"(d), "l"(src));
}
#define CPA_COMMIT() asm volatile("cp.async.commit_group;")
#define CPA_WAIT(n)  asm volatile("cp.async.wait_group %0;" :: "n"(n))

// XOR swizzle: flip bits [3:5] of the column by row&7. 16B groups (c%4==0)
// stay contiguous (only bits >=3 flip), so cp.async 16B works on SW addresses.
#define SW(r, c) ((r)*64 + ((c) ^ (((r)&7) << 3)))
#define FU(x) __float_as_uint(x)

// ---------------------------------------------------------------------------
// Kernel 0: fused tf32 pre-rounding pass (one launch, segmented).
// ---------------------------------------------------------------------------
#define NX4 ((B*S*D)/4)     // 1,048,576 float4 per x tensor
#define NW4 ((H*D*A)/4)     // 65,536 per qkv weight; wo is HA*D/4 = same
__global__ void round_all_kernel(const float* __restrict__ q,
                                 const float* __restrict__ k,
                                 const float* __restrict__ v,
                                 const float* __restrict__ wq,
                                 const float* __restrict__ wk,
                                 const float* __restrict__ wv,
                                 const float* __restrict__ wo)
{
    int i = blockIdx.x * blockDim.x + threadIdx.x;
    const float* src; float* dst; int off;
    if      (i < 1*NX4)       { src = q;  dst = g_xq; off = i;           }
    else if (i < 2*NX4)       { src = k;  dst = g_xk; off = i - 1*NX4;   }
    else if (i < 3*NX4)       { src = v;  dst = g_xv; off = i - 2*NX4;   }
    else if (i < 3*NX4+1*NW4) { src = wq; dst = g_wq; off = i - 3*NX4;         }
    else if (i < 3*NX4+2*NW4) { src = wk; dst = g_wk; off = i - 3*NX4 - 1*NW4; }
    else if (i < 3*NX4+3*NW4) { src = wv; dst = g_wv; off = i - 3*NX4 - 2*NW4; }
    else if (i < 3*NX4+4*NW4) { src = wo; dst = g_wo; off = i - 3*NX4 - 3*NW4; }
    else return;
    float4 val = ((const float4*)src)[off];
    val.x = __uint_as_float(f2tf(val.x));
    val.y = __uint_as_float(f2tf(val.y));
    val.z = __uint_as_float(f2tf(val.z));
    val.w = __uint_as_float(f2tf(val.w));
    ((float4*)dst)[off] = val;
}

// ---------------------------------------------------------------------------
// Kernel 1: fused QKV projection, tf32, cp.async double-buffered.
// CTA = 128(M) x 64(N=A), 4 warps x 32 rows. grid: (S/128, 3*B*H).
// ---------------------------------------------------------------------------
__global__ void __launch_bounds__(128) proj_tf32_kernel(
    const float* __restrict__ bq, const float* __restrict__ bk,
    const float* __restrict__ bv)
{
    extern __shared__ float sm[];
    float* Xb[2] = { sm,          sm + 8192  };
    float* Wb[2] = { sm + 16384,  sm + 20480 };

    const int z  = blockIdx.y;
    const int p  = z / (B*H);
    const int bh = z % (B*H);
    const int b  = bh / H;
    const int h  = bh % H;

    const float* x    = (p == 0 ? g_xq : p == 1 ? g_xk : g_xv) + (size_t)b * S * D;
    const float* W    = (p == 0 ? g_wq : p == 1 ? g_wk : g_wv) + (size_t)h * D * A;
    const float* bias = (p == 0 ? bq   : p == 1 ? bk   : bv)   + h * A;
    float* out        = (p == 0 ? g_q  : p == 1 ? g_k  : g_v)  + (size_t)bh * S * A;

    const int s0   = blockIdx.x * 128;
    const int tid  = threadIdx.x;
    const int warp = tid >> 5;
    const int lane = tid & 31;
    const int grp  = lane >> 2;
    const int qr   = lane & 3;

    float acc[2][8][4];
    #pragma unroll
    for (int g = 0; g < 2; g++)
        #pragma unroll
        for (int nt = 0; nt < 8; nt++)
            #pragma unroll
            for (int j = 0; j < 4; j++) acc[g][nt][j] = 0.0f;

    {
        #pragma unroll
        for (int u = 0; u < 16; u++) {
            int idx = (u * 128 + tid) * 4;
            int r = idx >> 6, c = idx & 63;
            cpa16(&Xb[0][SW(r, c)], &x[(size_t)(s0 + r) * D + c]);
        }
        #pragma unroll
        for (int u = 0; u < 8; u++) {
            int idx = (u * 128 + tid) * 4;
            int r = idx >> 6, c = idx & 63;
            cpa16(&Wb[0][SW(r, c)], &W[(size_t)r * A + c]);
        }
        CPA_COMMIT();
    }

    for (int ci = 0; ci < 8; ci++) {
        if (ci < 7) {
            int k0 = (ci + 1) * 64;
            float* Xd = Xb[(ci + 1) & 1];
            float* Wd = Wb[(ci + 1) & 1];
            #pragma unroll
            for (int u = 0; u < 16; u++) {
                int idx = (u * 128 + tid) * 4;
                int r = idx >> 6, c = idx & 63;
                cpa16(&Xd[SW(r, c)], &x[(size_t)(s0 + r) * D + k0 + c]);
            }
            #pragma unroll
            for (int u = 0; u < 8; u++) {
                int idx = (u * 128 + tid) * 4;
                int r = idx >> 6, c = idx & 63;
                cpa16(&Wd[SW(r, c)], &W[(size_t)(k0 + r) * A + c]);
            }
            CPA_COMMIT();
            CPA_WAIT(1);
        } else {
            CPA_WAIT(0);
        }
        __syncthreads();

        const float* Xd = Xb[ci & 1];
        const float* Wd = Wb[ci & 1];
        #pragma unroll
        for (int ks = 0; ks < 8; ks++) {
            unsigned af[2][4];
            #pragma unroll
            for (int g = 0; g < 2; g++) {
                int rb = warp * 32 + g * 16 + grp;
                af[g][0] = FU(Xd[SW(rb,     ks*8 + qr)]);
                af[g][1] = FU(Xd[SW(rb + 8, ks*8 + qr)]);
                af[g][2] = FU(Xd[SW(rb,     ks*8 + qr + 4)]);
                af[g][3] = FU(Xd[SW(rb + 8, ks*8 + qr + 4)]);
            }
            #pragma unroll
            for (int nt = 0; nt < 8; nt++) {
                unsigned b0 = FU(Wd[SW(ks*8 + qr,     nt*8 + grp)]);
                unsigned b1 = FU(Wd[SW(ks*8 + qr + 4, nt*8 + grp)]);
                mma_tf32(acc[0][nt], af[0], b0, b1);
                mma_tf32(acc[1][nt], af[1], b0, b1);
            }
        }
        __syncthreads();
    }

    #pragma unroll
    for (int g = 0; g < 2; g++) {
        int rb = warp * 32 + g * 16 + grp;
        #pragma unroll
        for (int nt = 0; nt < 8; nt++) {
            int c = nt*8 + 2*qr;
            float2 bv2 = make_float2(bias[c], bias[c+1]);
            *(float2*)&out[(size_t)(s0 + rb) * A + c] = make_float2(
                __uint_as_float(f2tf(acc[g][nt][0] + bv2.x)),
                __uint_as_float(f2tf(acc[g][nt][1] + bv2.y)));
            *(float2*)&out[(size_t)(s0 + rb + 8) * A + c] = make_float2(
                __uint_as_float(f2tf(acc[g][nt][2] + bv2.x)),
                __uint_as_float(f2tf(acc[g][nt][3] + bv2.y)));
        }
    }
}

// ---------------------------------------------------------------------------
// Kernel 2: flash attention, tf32. 128 query rows per CTA (32 rows/warp).
// Changes vs R6: (a) P C-frag -> A-frag via quad shfl (no Ps smem, same tf32
// rounding point -> bit-identical numerics); (b) K/V double-buffered cp.async.
// Smem 96KB: Qs 128x64 | K0,K1 64x64 | V0,V1 64x64.
// Causal block-skip (j<=i masked); last CTA (row S-1 fully masked -> uniform
// over ALL S keys) keeps the full loop. grid: (S/128, B*H), 128 threads.
// ---------------------------------------------------------------------------
__global__ void __launch_bounds__(128) attn_mma_kernel()
{
    extern __shared__ float sm[];
    float* Qs    = sm;                          // 128*64
    float* Kb[2] = { sm + 8192,  sm + 12288 };  // 64*64 each
    float* Vb[2] = { sm + 16384, sm + 20480 };  // 64*64 each

    const int bh = blockIdx.y;
    const int b  = bh / H;
    const int h  = bh % H;
    const int qb = blockIdx.x * 128;
    const int tid  = threadIdx.x;
    const int warp = tid >> 5;
    const int lane = tid & 31;
    const int grp  = lane >> 2;
    const int qr   = lane & 3;

    const float* kg = g_k + (size_t)bh * S * 64;
    const float* vg = g_v + (size_t)bh * S * 64;

    const int j_start = (qb == S - 128) ? 0 : qb;
    const int nb = (S - j_start) >> 6;

    // ---- stage Q (scaled by 1/sqrt(A); exact for tf32 values) ----
    const float* qg = g_q + ((size_t)bh * S + qb) * 64;
    #pragma unroll
    for (int u = 0; u < 16; u++) {
        int idx = (u * 128 + tid) * 4;
        int r = idx >> 6, c = idx & 63;
        float4 v = *(const float4*)&qg[idx];
        float* p = &Qs[SW(r, c)];
        p[0] = v.x * 0.125f; p[1] = v.y * 0.125f;
        p[2] = v.z * 0.125f; p[3] = v.w * 0.125f;
    }

    // ---- preload K/V block 0 ----
    {
        int j0 = j_start;
        #pragma unroll
        for (int u = 0; u < 8; u++) {
            int idx = (u * 128 + tid) * 4;
            int r = idx >> 6, c = idx & 63;
            cpa16(&Kb[0][SW(r, c)], &kg[(size_t)j0 * 64 + idx]);
            cpa16(&Vb[0][SW(r, c)], &vg[(size_t)j0 * 64 + idx]);
        }
        CPA_COMMIT();
    }

    float oacc[2][8][4];
    #pragma unroll
    for (int g = 0; g < 2; g++)
        #pragma unroll
        for (int nt = 0; nt < 8; nt++)
            #pragma unroll
            for (int j = 0; j < 4; j++) oacc[g][nt][j] = 0.0f;

    float m[4], l[4];
    #pragma unroll
    for (int q = 0; q < 4; q++) { m[q] = -INFINITY; l[q] = 0.0f; }

    for (int it = 0; it < nb; it++) {
        const int j0 = j_start + (it << 6);
        // ---- prefetch next block into the other buffer ----
        if (it + 1 < nb) {
            int jn = j0 + 64;
            float* Kd = Kb[(it + 1) & 1];
            float* Vd = Vb[(it + 1) & 1];
            #pragma unroll
            for (int u = 0; u < 8; u++) {
                int idx = (u * 128 + tid) * 4;
                int r = idx >> 6, c = idx & 63;
                cpa16(&Kd[SW(r, c)], &kg[(size_t)jn * 64 + idx]);
                cpa16(&Vd[SW(r, c)], &vg[(size_t)jn * 64 + idx]);
            }
            CPA_COMMIT();
            CPA_WAIT(1);
        } else {
            CPA_WAIT(0);
        }
        __syncthreads();   // current block visible; also covers Qs on it=0

        const float* Ks = Kb[it & 1];
        const float* Vs = Vb[it & 1];

        // ---- S = Q * K^T ----
        float sacc[2][8][4];
        #pragma unroll
        for (int g = 0; g < 2; g++)
            #pragma unroll
            for (int nt = 0; nt < 8; nt++)
                #pragma unroll
                for (int j = 0; j < 4; j++) sacc[g][nt][j] = 0.0f;

        #pragma unroll
        for (int ks = 0; ks < 8; ks++) {
            unsigned qa[2][4];
            #pragma unroll
            for (int g = 0; g < 2; g++) {
                int rb = warp * 32 + g * 16 + grp;
                qa[g][0] = FU(Qs[SW(rb,     ks*8 + qr)]);
                qa[g][1] = FU(Qs[SW(rb + 8, ks*8 + qr)]);
                qa[g][2] = FU(Qs[SW(rb,     ks*8 + qr + 4)]);
                qa[g][3] = FU(Qs[SW(rb + 8, ks*8 + qr + 4)]);
            }
            #pragma unroll
            for (int nt = 0; nt < 8; nt++) {
                unsigned b0 = FU(Ks[SW(nt*8 + grp, ks*8 + qr)]);
                unsigned b1 = FU(Ks[SW(nt*8 + grp, ks*8 + qr + 4)]);
                mma_tf32(sacc[0][nt], qa[0], b0, b1);
                mma_tf32(sacc[1][nt], qa[1], b0, b1);
            }
        }

        // ---- mask + online softmax; P kept in registers (tf32) ----
        unsigned pu[2][8][4];
        #pragma unroll
        for (int g = 0; g < 2; g++) {
            const int iA = qb + warp * 32 + g * 16 + grp;
            const int iB = iA + 8;
            float tmaxA = -INFINITY, tmaxB = -INFINITY;
            #pragma unroll
            for (int nt = 0; nt < 8; nt++) {
                int j = j0 + nt*8 + 2*qr;
                if (j     <= iA) sacc[g][nt][0] = -1.0e9f;
                if (j + 1 <= iA) sacc[g][nt][1] = -1.0e9f;
                if (j     <= iB) sacc[g][nt][2] = -1.0e9f;
                if (j + 1 <= iB) sacc[g][nt][3] = -1.0e9f;
                tmaxA = fmaxf(tmaxA, fmaxf(sacc[g][nt][0], sacc[g][nt][1]));
                tmaxB = fmaxf(tmaxB, fmaxf(sacc[g][nt][2], sacc[g][nt][3]));
            }
            tmaxA = fmaxf(tmaxA, __shfl_xor_sync(0xffffffffu, tmaxA, 1));
            tmaxA = fmaxf(tmaxA, __shfl_xor_sync(0xffffffffu, tmaxA, 2));
            tmaxB = fmaxf(tmaxB, __shfl_xor_sync(0xffffffffu, tmaxB, 1));
            tmaxB = fmaxf(tmaxB, __shfl_xor_sync(0xffffffffu, tmaxB, 2));

            float mnA = fmaxf(m[2*g],   tmaxA);
            float mnB = fmaxf(m[2*g+1], tmaxB);
            float crA = __expf(m[2*g]   - mnA);   // first block: exp(-inf)=0
            float crB = __expf(m[2*g+1] - mnB);
            l[2*g]   *= crA; l[2*g+1] *= crB;
            m[2*g]    = mnA; m[2*g+1]  = mnB;
            #pragma unroll
            for (int nt = 0; nt < 8; nt++) {
                oacc[g][nt][0] *= crA; oacc[g][nt][1] *= crA;
                oacc[g][nt][2] *= crB; oacc[g][nt][3] *= crB;
            }

            float lsA = 0.0f, lsB = 0.0f;
            #pragma unroll
            for (int nt = 0; nt < 8; nt++) {
                float p0 = __expf(sacc[g][nt][0] - mnA);
                float p1 = __expf(sacc[g][nt][1] - mnA);
                float p2 = __expf(sacc[g][nt][2] - mnB);
                float p3 = __expf(sacc[g][nt][3] - mnB);
                lsA += p0 + p1; lsB += p2 + p3;
                pu[g][nt][0] = f2tf(p0);
                pu[g][nt][1] = f2tf(p1);
                pu[g][nt][2] = f2tf(p2);
                pu[g][nt][3] = f2tf(p3);
            }
            l[2*g] += lsA; l[2*g+1] += lsB;
        }

        // ---- O += P * V ; P C-frag -> A-frag via quad shfl ----
        // P(row, key ks*8+mm) lives at lane (grp*4 + (mm>>1)), reg parity mm&1.
        const int srcLo = (lane & ~3) | (qr >> 1);
        const int srcHi = srcLo + 2;
        #pragma unroll
        for (int ks = 0; ks < 8; ks++) {
            unsigned pa[2][4];
            #pragma unroll
            for (int g = 0; g < 2; g++) {
                unsigned v0 = pu[g][ks][0], v1 = pu[g][ks][1];
                unsigned v2 = pu[g][ks][2], v3 = pu[g][ks][3];
                unsigned sA0 = __shfl_sync(0xffffffffu, v0, srcLo);
                unsigned sA1 = __shfl_sync(0xffffffffu, v1, srcLo);
                unsigned sB0 = __shfl_sync(0xffffffffu, v2, srcLo);
                unsigned sB1 = __shfl_sync(0xffffffffu, v3, srcLo);
                unsigned tA0 = __shfl_sync(0xffffffffu, v0, srcHi);
                unsigned tA1 = __shfl_sync(0xffffffffu, v1, srcHi);
                unsigned tB0 = __shfl_sync(0xffffffffu, v2, srcHi);
                unsigned tB1 = __shfl_sync(0xffffffffu, v3, srcHi);
                pa[g][0] = (qr & 1) ? sA1 : sA0;   // P(rowA, qr)
                pa[g][1] = (qr & 1) ? sB1 : sB0;   // P(rowB, qr)
                pa[g][2] = (qr & 1) ? tA1 : tA0;   // P(rowA, qr+4)
                pa[g][3] = (qr & 1) ? tB1 : tB0;   // P(rowB, qr+4)
            }
            #pragma unroll
            for (int nt = 0; nt < 8; nt++) {
                unsigned b0 = FU(Vs[SW(ks*8 + qr,     nt*8 + grp)]);
                unsigned b1 = FU(Vs[SW(ks*8 + qr + 4, nt*8 + grp)]);
                mma_tf32(oacc[0][nt], pa[0], b0, b1);
                mma_tf32(oacc[1][nt], pa[1], b0, b1);
            }
        }
        __syncthreads();   // all warps done with buf (it&1) before it+1 refills it
    }

    // ---- quad-reduce softmax denominators ----
    #pragma unroll
    for (int q = 0; q < 4; q++) {
        l[q] += __shfl_xor_sync(0xffffffffu, l[q], 1);
        l[q] += __shfl_xor_sync(0xffffffffu, l[q], 2);
    }

    // ---- epilogue: normalize, round to tf32, write head-concat layout ----
    #pragma unroll
    for (int g = 0; g < 2; g++) {
        const int iA = qb + warp * 32 + g * 16 + grp;
        const float invA = 1.0f / l[2*g];
        const float invB = 1.0f / l[2*g+1];
        float* obA = g_attn + ((size_t)b * S + iA) * HA + h * A;
        float* obB = g_attn + ((size_t)b * S + iA + 8) * HA + h * A;
        #pragma unroll
        for (int nt = 0; nt < 8; nt++) {
            int c = nt*8 + 2*qr;
            *(float2*)&obA[c] = make_float2(
                __uint_as_float(f2tf(oacc[g][nt][0] * invA)),
                __uint_as_float(f2tf(oacc[g][nt][1] * invA)));
            *(float2*)&obB[c] = make_float2(
                __uint_as_float(f2tf(oacc[g][nt][2] * invB)),
                __uint_as_float(f2tf(oacc[g][nt][3] * invB)));
        }
    }
}

// ---------------------------------------------------------------------------
// Kernel 3: output projection, tf32, cp.async double-buffered.
// out[M=B*S, N=D] = g_attn[M, HA] @ Wo[HA, D] + bo. grid: (D/64, B*S/128).
// ---------------------------------------------------------------------------
__global__ void __launch_bounds__(128) out_proj_tf32_kernel(
    const float* __restrict__ bo, float* __restrict__ out)
{
    extern __shared__ float sm[];
    float* Xb[2] = { sm,          sm + 8192  };
    float* Wb[2] = { sm + 16384,  sm + 20480 };

    const int n0 = blockIdx.x * 64;
    const int s0 = blockIdx.y * 128;
    const int tid  = threadIdx.x;
    const int warp = tid >> 5;
    const int lane = tid & 31;
    const int grp  = lane >> 2;
    const int qr   = lane & 3;

    float acc[2][8][4];
    #pragma unroll
    for (int g = 0; g < 2; g++)
        #pragma unroll
        for (int nt = 0; nt < 8; nt++)
            #pragma unroll
            for (int j = 0; j < 4; j++) acc[g][nt][j] = 0.0f;

    {
        #pragma unroll
        for (int u = 0; u < 16; u++) {
            int idx = (u * 128 + tid) * 4;
            int r = idx >> 6, c = idx & 63;
            cpa16(&Xb[0][SW(r, c)], &g_attn[(size_t)(s0 + r) * HA + c]);
        }
        #pragma unroll
        for (int u = 0; u < 8; u++) {
            int idx = (u * 128 + tid) * 4;
            int r = idx >> 6, c = idx & 63;
            cpa16(&Wb[0][SW(r, c)], &g_wo[(size_t)r * D + n0 + c]);
        }
        CPA_COMMIT();
    }

    for (int ci = 0; ci < 8; ci++) {
        if (ci < 7) {
            int k0 = (ci + 1) * 64;
            float* Xd = Xb[(ci + 1) & 1];
            float* Wd = Wb[(ci + 1) & 1];
            #pragma unroll
            for (int u = 0; u < 16; u++) {
                int idx = (u * 128 + tid) * 4;
                int r = idx >> 6, c = idx & 63;
                cpa16(&Xd[SW(r, c)], &g_attn[(size_t)(s0 + r) * HA + k0 + c]);
            }
            #pragma unroll
            for (int u = 0; u < 8; u++) {
                int idx = (u * 128 + tid) * 4;
                int r = idx >> 6, c = idx & 63;
                cpa16(&Wd[SW(r, c)], &g_wo[(size_t)(k0 + r) * D + n0 + c]);
            }
            CPA_COMMIT();
            CPA_WAIT(1);
        } else {
            CPA_WAIT(0);
        }
        __syncthreads();

        const float* Xd = Xb[ci & 1];
        const float* Wd = Wb[ci & 1];
        #pragma unroll
        for (int ks = 0; ks < 8; ks++) {
            unsigned af[2][4];
            #pragma unroll
            for (int g = 0; g < 2; g++) {
                int rb = warp * 32 + g * 16 + grp;
                af[g][0] = FU(Xd[SW(rb,     ks*8 + qr)]);
                af[g][1] = FU(Xd[SW(rb + 8, ks*8 + qr)]);
                af[g][2] = FU(Xd[SW(rb,     ks*8 + qr + 4)]);
                af[g][3] = FU(Xd[SW(rb + 8, ks*8 + qr + 4)]);
            }
            #pragma unroll
            for (int nt = 0; nt < 8; nt++) {
                unsigned b0 = FU(Wd[SW(ks*8 + qr,     nt*8 + grp)]);
                unsigned b1 = FU(Wd[SW(ks*8 + qr + 4, nt*8 + grp)]);
                mma_tf32(acc[0][nt], af[0], b0, b1);
                mma_tf32(acc[1][nt], af[1], b0, b1);
            }
        }
        __syncthreads();
    }

    #pragma unroll
    for (int g = 0; g < 2; g++) {
        int rb = warp * 32 + g * 16 + grp;
        #pragma unroll
        for (int nt = 0; nt < 8; nt++) {
            int c = nt*8 + 2*qr;
            float2 bv2 = make_float2(bo[n0 + c], bo[n0 + c + 1]);
            *(float2*)&out[(size_t)(s0 + rb) * D + n0 + c] =
                make_float2(acc[g][nt][0] + bv2.x, acc[g][nt][1] + bv2.y);
            *(float2*)&out[(size_t)(s0 + rb + 8) * D + n0 + c] =
                make_float2(acc[g][nt][2] + bv2.x, acc[g][nt][3] + bv2.y);
        }
    }
}

// ---------------------------------------------------------------------------
extern "C" void kernel_launch(void* const* d_in, const int* in_sizes, int n_in,
                              void* d_out, int out_size)
{
    const float* query = (const float*)d_in[0];
    const float* key   = (const float*)d_in[1];
    const float* value = (const float*)d_in[2];
    const float* Wq    = (const float*)d_in[3];
    const float* bq    = (const float*)d_in[4];
    const float* Wk    = (const float*)d_in[5];
    const float* bk    = (const float*)d_in[6];
    const float* Wv    = (const float*)d_in[7];
    const float* bv    = (const float*)d_in[8];
    const float* Wo    = (const float*)d_in[9];
    const float* bo    = (const float*)d_in[10];
    float* out = (float*)d_out;

    (void)in_sizes; (void)n_in; (void)out_size;

    // ---- fused tf32 pre-round of all inputs & weights (one launch) ----
    const int total4 = 3 * NX4 + 4 * NW4;
    round_all_kernel<<<(total4 + 255) / 256, 256>>>(query, key, value,
                                                    Wq, Wk, Wv, Wo);

    // dynamic smem attribute sets: idempotent, capture-safe, no allocation
    static const int SMEM96 = 24576 * (int)sizeof(float);   // 98304 B
    cudaFuncSetAttribute(proj_tf32_kernel,
                         cudaFuncAttributeMaxDynamicSharedMemorySize, SMEM96);
    cudaFuncSetAttribute(attn_mma_kernel,
                         cudaFuncAttributeMaxDynamicSharedMemorySize, SMEM96);
    cudaFuncSetAttribute(out_proj_tf32_kernel,
                         cudaFuncAttributeMaxDynamicSharedMemorySize, SMEM96);

    proj_tf32_kernel<<<dim3(S / 128, 3 * B * H), 128, SMEM96>>>(bq, bk, bv);

    attn_mma_kernel<<<dim3(S / 128, B * H), 128, SMEM96>>>();

    out_proj_tf32_kernel<<<dim3(D / 64, (B * S) / 128), 128, SMEM96>>>(bo, out);
}